// round 11
// baseline (speedup 1.0000x reference)
#include <cuda_runtime.h>
#include <cuda_fp16.h>
#include <cstdint>

#define N_ROWS 100000
#define IN_CH  256
#define OUT_CH 128
#define KVOL   8

#define BM 128
#define BK 32
#define NCHUNK 8                 // IN_CH / BK
#define MTILES 782               // ceil(100000/128)
#define KB_PER_CTA 2
#define NKB2 (KVOL / KB_PER_CTA) // 4

// fragment-packed chunk tiles, half2 units (uint32)
// A chunk: [ks(2)][m16(8)][g(8)][l4(4)][reg(4)] = 2048 u32 = 8KB; full tile 8 chunks = 64KB
// B chunk: [ks(2)][col(128)][l4(4)][j(2)]        = 2048 u32 = 8KB
#define CH_U32 2048
#define NBUF_B 3
#define A_U32 (NCHUNK * CH_U32)                 // 16384 u32 = 64KB
#define SM_U32 (A_U32 + NBUF_B * CH_U32)        // 22528 u32 = 88KB

__device__ __align__(16) uint32_t g_Wt[KVOL * NCHUNK * CH_U32];     // 512KB

__device__ __forceinline__ uint32_t pack_h2(float a, float b) {
    __half2 h = __floats2half2_rn(a, b);
    return *reinterpret_cast<uint32_t*>(&h);
}
__device__ __forceinline__ uint32_t smem_u32(const void* p) {
    uint32_t a;
    asm("{ .reg .u64 t; cvta.to.shared.u64 t, %1; cvt.u32.u64 %0, t; }" : "=r"(a) : "l"(p));
    return a;
}
__device__ __forceinline__ int aIdx(int ks, int m16, int g, int l4, int reg) {
    return (((ks * 8 + m16) * 8 + g) * 4 + l4) * 4 + reg;
}

// ---------------------------------------------------------------------------
// pack W: [8][256][128] fp32 -> fp16 B fragments per [kb][chunk] (proven)
__global__ __launch_bounds__(256)
void prep_Wt(const float* __restrict__ W)
{
    int d = blockIdx.x * blockDim.x + threadIdx.x;   // 0 .. 8*8*2048-1
    int kb = d >> 14;
    int c  = (d >> 11) & 7;
    int r  = d & 2047;
    int j   = r & 1;
    int l4  = (r >> 1) & 3;
    int col = (r >> 3) & 127;
    int ks  = r >> 10;
    int k0 = c * BK + ks * 16 + j * 8 + l4 * 2;
    float w0 = W[((size_t)kb * IN_CH + k0) * OUT_CH + col];
    float w1 = W[((size_t)kb * IN_CH + k0 + 1) * OUT_CH + col];
    g_Wt[d] = pack_h2(w0, w1);
}

// ---------------------------------------------------------------------------
// 4 warps, 64x64 warp tiles. A tile converted fp32->fp16 fragments into smem
// ONCE in the prologue; mainloop runs 2 kb values against it (B streamed).
// kb2==0 CTAs also emit coords in the epilogue.
__global__ __launch_bounds__(128, 2)
void gemm_fp16(const float* __restrict__ feats,
               float* __restrict__ out,
               const int* __restrict__ coords,
               float* __restrict__ outc,
               int do_coords)
{
    extern __shared__ uint32_t smem[];   // [A fragments 16384][B ring 3*2048]

    const int tid  = threadIdx.x;
    const int kb2  = blockIdx.x;            // 0..3 -> kb = 2*kb2 + kbi
    const int tile = blockIdx.y;
    const int m0   = tile * BM;
    const int lane = tid & 31;
    const int wid  = tid >> 5;
    const int wm   = (wid >> 1) * 64;
    const int wn   = (wid & 1) * 64;
    const int m16b = wm >> 4;               // 0 or 4
    const int g    = lane >> 2;
    const int l4   = lane & 3;

    const uint32_t sB = smem_u32(smem) + A_U32 * 4;

    auto cpB = [&](int it, int buf) {       // it = kbi*8 + c
        const int kb = kb2 * KB_PER_CTA + (it >> 3);
        const int c  = it & 7;
        const uint32_t* srcB = g_Wt + ((size_t)kb * NCHUNK + c) * CH_U32;
        uint32_t dB = sB + (buf * CH_U32 + tid * 4) * 4;
        #pragma unroll
        for (int i = 0; i < 4; ++i) {
            asm volatile("cp.async.cg.shared.global [%0], [%1], 16;"
                         :: "r"(dB + i * 2048), "l"(srcB + tid * 4 + i * 512) : "memory");
        }
        asm volatile("cp.async.commit_group;" ::: "memory");
    };

    // start B pipeline before the A-conversion prologue (overlap)
    cpB(0, 0);
    cpB(1, 1);

    // ---- prologue: convert this tile's A (fp32) into fragment smem ----
    {
        const int pr   = tid >> 1;          // 0..63
        const int sm16 = pr >> 3;
        const int sg   = pr & 7;
        const int ks   = tid & 1;
        const int r0   = m0 + sm16 * 16 + sg;
        const int r1   = r0 + 8;
        #pragma unroll 1
        for (int c = 0; c < NCHUNK; ++c) {
            const int k0 = c * BK + ks * 16;
            float4 a0, a1, a2, a3, b0, b1, b2, b3;
            const float4 z = make_float4(0.f, 0.f, 0.f, 0.f);
            if (r0 < N_ROWS) {
                const float4* p = (const float4*)(feats + (size_t)r0 * IN_CH + k0);
                a0 = p[0]; a1 = p[1]; a2 = p[2]; a3 = p[3];
            } else { a0 = a1 = a2 = a3 = z; }
            if (r1 < N_ROWS) {
                const float4* p = (const float4*)(feats + (size_t)r1 * IN_CH + k0);
                b0 = p[0]; b1 = p[1]; b2 = p[2]; b3 = p[3];
            } else { b0 = b1 = b2 = b3 = z; }
            uint32_t* dst = smem + c * CH_U32;
            uint4 v;
            // l4=0: lo=(k0,k1), hi=(k8,k9)
            v.x = pack_h2(a0.x, a0.y); v.y = pack_h2(b0.x, b0.y);
            v.z = pack_h2(a2.x, a2.y); v.w = pack_h2(b2.x, b2.y);
            *(uint4*)(dst + aIdx(ks, sm16, sg, 0, 0)) = v;
            // l4=1
            v.x = pack_h2(a0.z, a0.w); v.y = pack_h2(b0.z, b0.w);
            v.z = pack_h2(a2.z, a2.w); v.w = pack_h2(b2.z, b2.w);
            *(uint4*)(dst + aIdx(ks, sm16, sg, 1, 0)) = v;
            // l4=2
            v.x = pack_h2(a1.x, a1.y); v.y = pack_h2(b1.x, b1.y);
            v.z = pack_h2(a3.x, a3.y); v.w = pack_h2(b3.x, b3.y);
            *(uint4*)(dst + aIdx(ks, sm16, sg, 2, 0)) = v;
            // l4=3
            v.x = pack_h2(a1.z, a1.w); v.y = pack_h2(b1.z, b1.w);
            v.z = pack_h2(a3.z, a3.w); v.w = pack_h2(b3.z, b3.w);
            *(uint4*)(dst + aIdx(ks, sm16, sg, 3, 0)) = v;
        }
    }
    __syncthreads();   // A fragments visible to all warps

    float acc[4][8][4];
    #pragma unroll
    for (int mt = 0; mt < 4; ++mt)
        #pragma unroll
        for (int nt = 0; nt < 8; ++nt)
            #pragma unroll
            for (int i = 0; i < 4; ++i) acc[mt][nt][i] = 0.f;

    auto epilogue = [&](int kb) {
        #pragma unroll
        for (int mt = 0; mt < 4; ++mt) {
            const int r0 = m0 + wm + mt * 16 + g;
            const int r1 = r0 + 8;
            #pragma unroll
            for (int nt = 0; nt < 8; ++nt) {
                const int col = wn + nt * 8 + l4 * 2;
                if (r0 < N_ROWS) {
                    *(float2*)(out + ((size_t)r0 * KVOL + kb) * OUT_CH + col) =
                        make_float2(acc[mt][nt][0], acc[mt][nt][1]);
                }
                if (r1 < N_ROWS) {
                    *(float2*)(out + ((size_t)r1 * KVOL + kb) * OUT_CH + col) =
                        make_float2(acc[mt][nt][2], acc[mt][nt][3]);
                }
                #pragma unroll
                for (int i = 0; i < 4; ++i) acc[mt][nt][i] = 0.f;
            }
        }
    };

    const int NIT = KB_PER_CTA * NCHUNK;   // 16
    #pragma unroll 1
    for (int it = 0; it < NIT; ++it) {
        const int buf = it % NBUF_B;
        const int c   = it & 7;
        if (it < NIT - 1) asm volatile("cp.async.wait_group 1;" ::: "memory");
        else              asm volatile("cp.async.wait_group 0;" ::: "memory");
        __syncthreads();   // single barrier (3-buffer ring covers WAR)
        if (it + 2 < NIT) cpB(it + 2, (it + 2) % NBUF_B);

        const uint32_t* Ab = smem + c * CH_U32;
        const uint32_t* Bb = smem + A_U32 + buf * CH_U32;
        #pragma unroll
        for (int ks = 0; ks < 2; ++ks) {
            uint4 a[4];
            #pragma unroll
            for (int mt = 0; mt < 4; ++mt)
                a[mt] = *(const uint4*)(Ab + aIdx(ks, m16b + mt, g, l4, 0));
            #pragma unroll
            for (int nt = 0; nt < 8; ++nt) {
                uint2 b = *(const uint2*)(Bb + ((ks * 128 + wn + nt * 8 + g) * 4 + l4) * 2);
                #pragma unroll
                for (int mt = 0; mt < 4; ++mt) {
                    asm volatile(
                        "mma.sync.aligned.m16n8k16.row.col.f32.f16.f16.f32 "
                        "{%0,%1,%2,%3}, {%4,%5,%6,%7}, {%8,%9}, {%0,%1,%2,%3};\n"
                        : "+f"(acc[mt][nt][0]), "+f"(acc[mt][nt][1]),
                          "+f"(acc[mt][nt][2]), "+f"(acc[mt][nt][3])
                        : "r"(a[mt].x), "r"(a[mt].y), "r"(a[mt].z), "r"(a[mt].w),
                          "r"(b.x), "r"(b.y));
                }
            }
        }

        if (c == 7) epilogue(kb2 * KB_PER_CTA + (it >> 3));
    }

    // coords for this tile's 128 rows (kb2==0 CTAs only), 1 row per thread
    if (do_coords && kb2 == 0) {
        const int n = m0 + tid;
        if (n < N_ROWS) {
            float cx = (float)(2 * __ldg(coords + n * 3 + 0));
            float cy = (float)(2 * __ldg(coords + n * 3 + 1));
            float cz = (float)(2 * __ldg(coords + n * 3 + 2));
            float4 v[6];
            float* vf = (float*)v;
            #pragma unroll
            for (int k = 0; k < 8; ++k) {
                vf[k * 3 + 0] = cx + (float)((k >> 2) & 1);
                vf[k * 3 + 1] = cy + (float)((k >> 1) & 1);
                vf[k * 3 + 2] = cz + (float)(k & 1);
            }
            float4* dst = (float4*)(outc + (size_t)n * 24);
            #pragma unroll
            for (int i = 0; i < 6; ++i) dst[i] = v[i];
        }
    }
}

// ---------------------------------------------------------------------------
extern "C" void kernel_launch(void* const* d_in, const int* in_sizes, int n_in,
                              void* d_out, int out_size)
{
    const float* feats  = nullptr;
    const int*   coords = nullptr;
    const float* W      = nullptr;
    for (int i = 0; i < n_in; ++i) {
        if      (in_sizes[i] == N_ROWS * IN_CH)        feats  = (const float*)d_in[i];
        else if (in_sizes[i] == N_ROWS * 3)            coords = (const int*)d_in[i];
        else if (in_sizes[i] == KVOL * IN_CH * OUT_CH) W      = (const float*)d_in[i];
    }
    float* out = (float*)d_out;

    cudaFuncSetAttribute(gemm_fp16,
                         cudaFuncAttributeMaxDynamicSharedMemorySize, SM_U32 * 4);

    prep_Wt<<<(KVOL * NCHUNK * CH_U32) / 256, 256>>>(W);

    const long long featsN = (long long)N_ROWS * KVOL * OUT_CH;
    const long long coordN = (long long)N_ROWS * KVOL * 3;
    const int want_coords =
        ((long long)out_size >= featsN + coordN && coords != nullptr) ? 1 : 0;

    dim3 grid(NKB2, MTILES);   // kb2 fastest: 4 CTAs share each A tile in L2
    gemm_fp16<<<grid, 128, SM_U32 * 4>>>(feats, out, coords, out + featsN, want_coords);
}